// round 5
// baseline (speedup 1.0000x reference)
#include <cuda_runtime.h>

#define NU 8000
#define NI 4000
#define NN 12000
#define DD 64
#define NE 300000
#define WORDS 375          // ceil(12000/32)
#define WROW  376          // padded row stride in words (16B aligned rows)
#define WPT   6            // 64 threads * 6 = 384 >= 376
#define MAXNB 768          // max unique neighbors per row (mean ~50, huge margin)

// Scratch (device globals only — no allocation allowed)
__device__ unsigned g_adj[NN * WROW];     // ~18 MB bitmask adjacency
__device__ float    g_dinv[NN];           // 1/sqrt(max(deg,1))
__device__ float    g_bufA[NN * DD];
__device__ float    g_bufB[NN * DD];
__device__ float    g_acc [NN * DD];

__global__ void k_zero_adj() {
    int i = blockIdx.x * blockDim.x + threadIdx.x;
    const int n4 = NN * WROW / 4;           // 1,128,000 exactly
    if (i < n4) ((uint4*)g_adj)[i] = make_uint4(0u, 0u, 0u, 0u);
}

__global__ void k_set_edges(const int* __restrict__ ei) {
    int e = blockIdx.x * blockDim.x + threadIdx.x;
    if (e >= NE) return;
    int a = ei[e];
    int b = ei[NE + e];
    atomicOr(&g_adj[a * WROW + (b >> 5)], 1u << (b & 31));
    atomicOr(&g_adj[b * WROW + (a >> 5)], 1u << (a & 31));
}

__global__ void k_degree() {
    int gw   = (blockIdx.x * blockDim.x + threadIdx.x) >> 5;
    int lane = threadIdx.x & 31;
    if (gw >= NN) return;
    const unsigned* row = &g_adj[gw * WROW];
    int c = 0;
    for (int w = lane; w < WORDS; w += 32) c += __popc(row[w]);
    #pragma unroll
    for (int o = 16; o; o >>= 1) c += __shfl_xor_sync(0xffffffffu, c, o);
    if (lane == 0) g_dinv[gw] = rsqrtf(fmaxf((float)c, 1.0f));
}

__global__ void k_init(const float* __restrict__ ue, const float* __restrict__ ie) {
    int i = blockIdx.x * blockDim.x + threadIdx.x;
    if (i >= NN * DD) return;
    float v = (i < NU * DD) ? ue[i] : ie[i - NU * DD];
    g_bufA[i] = v;
    g_acc[i]  = v;
}

// One 64-thread block per row. phase: 0 = A->B, 1 = B->A, 2 = A->B (+final out)
__global__ __launch_bounds__(64) void k_spmm(int phase, float* __restrict__ dout) {
    const float* __restrict__ x = (phase == 1) ? g_bufB : g_bufA;
    float*       __restrict__ y = (phase == 1) ? g_bufA : g_bufB;

    int row = blockIdx.x;
    int t   = threadIdx.x;                 // 0..63 (also the feature dim)

    __shared__ int   s_j[MAXNB];
    __shared__ float s_w[MAXNB];
    __shared__ int   s_wsum[2];

    const unsigned* __restrict__ arow = &g_adj[row * WROW];

    // ---- phase 1: extract set bits into smem lists (deterministic layout) ----
    unsigned w[WPT];
    int c = 0;
    #pragma unroll
    for (int k = 0; k < WPT; k++) {
        int idx = t + 64 * k;              // coalesced across the warp
        unsigned v = (idx < WORDS) ? arow[idx] : 0u;
        w[k] = v;
        c += __popc(v);
    }
    int lane = t & 31, wid = t >> 5;
    int sc = c;                             // inclusive scan within warp
    #pragma unroll
    for (int o = 1; o < 32; o <<= 1) {
        int n = __shfl_up_sync(0xffffffffu, sc, o);
        if (lane >= o) sc += n;
    }
    if (lane == 31) s_wsum[wid] = sc;
    __syncthreads();
    int base  = (sc - c) + (wid ? s_wsum[0] : 0);
    int total = s_wsum[0] + s_wsum[1];

    #pragma unroll
    for (int k = 0; k < WPT; k++) {
        unsigned bits  = w[k];
        int      jbase = (t + 64 * k) * 32;
        while (bits) {
            int b = __ffs(bits) - 1;
            bits &= bits - 1;
            int j = jbase + b;
            s_j[base] = j;
            s_w[base] = g_dinv[j];
            base++;
        }
    }
    __syncthreads();

    // ---- phase 2: thread t accumulates feature dim t over the neighbor list ----
    float a = 0.0f;
    int k = 0;
    for (; k + 4 <= total; k += 4) {
        int   j0 = s_j[k],   j1 = s_j[k+1], j2 = s_j[k+2], j3 = s_j[k+3];
        float w0 = s_w[k],   w1 = s_w[k+1], w2 = s_w[k+2], w3 = s_w[k+3];
        float x0 = x[j0 * DD + t];
        float x1 = x[j1 * DD + t];
        float x2 = x[j2 * DD + t];
        float x3 = x[j3 * DD + t];
        a += w0 * x0;
        a += w1 * x1;
        a += w2 * x2;
        a += w3 * x3;
    }
    for (; k < total; k++) a += s_w[k] * x[s_j[k] * DD + t];

    float out = a * g_dinv[row];
    int   o   = row * DD + t;
    y[o] = out;
    float acc = g_acc[o] + out;
    g_acc[o] = acc;
    if (dout) dout[o] = acc * 0.25f;
}

extern "C" void kernel_launch(void* const* d_in, const int* in_sizes, int n_in,
                              void* d_out, int out_size) {
    const int*   ei = (const int*)  d_in[0];   // edge_index int32 (2, NE)
    const float* ue = (const float*)d_in[1];   // user_emb (8000, 64)
    const float* ie = (const float*)d_in[2];   // item_emb (4000, 64)
    float* out = (float*)d_out;

    k_zero_adj <<<(NN * WROW / 4 + 255) / 256, 256>>>();
    k_set_edges<<<(NE + 255) / 256, 256>>>(ei);
    k_degree   <<<(NN * 32 + 255) / 256, 256>>>();
    k_init     <<<(NN * DD + 255) / 256, 256>>>(ue, ie);

    k_spmm<<<NN, 64>>>(0, nullptr);   // layer 1: A -> B
    k_spmm<<<NN, 64>>>(1, nullptr);   // layer 2: B -> A
    k_spmm<<<NN, 64>>>(2, out);       // layer 3: A -> B, write acc/4
}

// round 7
// speedup vs baseline: 1.7822x; 1.7822x over previous
#include <cuda_runtime.h>

#define NU 8000
#define NI 4000
#define NN 12000
#define DD 64
#define NE 300000
#define WORDS 375          // ceil(12000/32)
#define WROW  376          // padded row stride in words
#define WPT   6            // 64 threads * 6 = 384 >= 376
#define CSTRIDE 128        // max unique neighbors per row (mean ~50, 11-sigma margin)
#define RPB   8            // rows per block in spmm (128 threads, 16 thr/row)

// Scratch (device globals only — referenced ONLY from device code)
__device__ unsigned g_adj[NN * WROW];       // 18 MB bitmask adjacency
__device__ int      g_csr[NN * CSTRIDE];    // 6.1 MB column indices
__device__ int      g_cnt[NN];
__device__ float    g_rdeg[NN];             // 1/max(deg,1)
__device__ float    g_sqdeg[NN];            // sqrt(max(deg,1))
__device__ float4   g_u0[NN * 16];          // u_l = D^{-1/2} x_l  (float4-aligned)
__device__ float4   g_u1[NN * 16];
__device__ float4   g_u2[NN * 16];

__global__ void k_zero_adj() {
    int i = blockIdx.x * blockDim.x + threadIdx.x;
    const int n4 = NN * WROW / 4;           // 1,128,000 exactly
    if (i < n4) ((uint4*)g_adj)[i] = make_uint4(0u, 0u, 0u, 0u);
}

__global__ void k_set_edges(const int* __restrict__ ei) {
    int e = blockIdx.x * blockDim.x + threadIdx.x;
    if (e >= NE) return;
    int a = ei[e];
    int b = ei[NE + e];
    atomicOr(&g_adj[a * WROW + (b >> 5)], 1u << (b & 31));
    atomicOr(&g_adj[b * WROW + (a >> 5)], 1u << (a & 31));
}

// One 64-thread block per row: extract bitmask row -> CSR, compute degree
// scalars, and write u0 = rsqrt(deg) * embed. Deterministic (warp prefix sum).
__global__ __launch_bounds__(64) void k_build(const float* __restrict__ ue,
                                              const float* __restrict__ ie) {
    int row = blockIdx.x;
    int t   = threadIdx.x;

    __shared__ int   s_wsum[2];
    __shared__ float s_dinv;

    const unsigned* __restrict__ arow = &g_adj[row * WROW];

    unsigned w[WPT];
    int c = 0;
    #pragma unroll
    for (int k = 0; k < WPT; k++) {
        int idx = t + 64 * k;                      // coalesced
        unsigned v = (idx < WORDS) ? arow[idx] : 0u;
        w[k] = v;
        c += __popc(v);
    }
    int lane = t & 31, wid = t >> 5;
    int sc = c;
    #pragma unroll
    for (int o = 1; o < 32; o <<= 1) {
        int n = __shfl_up_sync(0xffffffffu, sc, o);
        if (lane >= o) sc += n;
    }
    if (lane == 31) s_wsum[wid] = sc;
    __syncthreads();
    int base  = (sc - c) + (wid ? s_wsum[0] : 0);
    int total = s_wsum[0] + s_wsum[1];

    int* __restrict__ cr = &g_csr[row * CSTRIDE];
    #pragma unroll
    for (int k = 0; k < WPT; k++) {
        unsigned bits  = w[k];
        int      jbase = (t + 64 * k) * 32;
        while (bits) {
            int b = __ffs(bits) - 1;
            bits &= bits - 1;
            if (base < CSTRIDE) cr[base] = jbase + b;
            base++;
        }
    }

    if (t == 0) {
        float deg = fmaxf((float)total, 1.0f);
        g_cnt[row]   = (total < CSTRIDE) ? total : CSTRIDE;
        g_rdeg[row]  = 1.0f / deg;
        g_sqdeg[row] = sqrtf(deg);
        s_dinv       = rsqrtf(deg);
    }
    __syncthreads();

    float e = (row < NU) ? ue[row * DD + t] : ie[(row - NU) * DD + t];
    ((float*)g_u0)[row * DD + t] = e * s_dinv;
}

// SpMM on the transformed recursion: uout[i] = rdeg[i] * sum_{j in N(i)} uin[j].
// 128 threads = 8 rows x 16 threads; each thread owns one float4 (4 dims).
// layer 0: u0->u1, layer 1: u1->u2, layer 2: u2->(u3, fused final output)
__global__ __launch_bounds__(128) void k_spmm(int layer, float* __restrict__ dout) {
    const float4* __restrict__ xin =
        (layer == 0) ? (const float4*)g_u0 :
        (layer == 1) ? (const float4*)g_u1 : (const float4*)g_u2;
    float4* __restrict__ uout = (layer == 0) ? g_u1 : g_u2;  // unused on layer 2

    int grp = threadIdx.x >> 4;                    // row within block, 0..7
    int l4  = threadIdx.x & 15;                    // float4 slot, 0..15
    int row = blockIdx.x * RPB + grp;

    int n = g_cnt[row];
    const int* __restrict__ cj = &g_csr[row * CSTRIDE];

    float4 a = make_float4(0.f, 0.f, 0.f, 0.f);
    int k = 0;
    for (; k + 4 <= n; k += 4) {
        int j0 = cj[k], j1 = cj[k+1], j2 = cj[k+2], j3 = cj[k+3];
        float4 v0 = xin[j0 * 16 + l4];
        float4 v1 = xin[j1 * 16 + l4];
        float4 v2 = xin[j2 * 16 + l4];
        float4 v3 = xin[j3 * 16 + l4];
        a.x += v0.x; a.y += v0.y; a.z += v0.z; a.w += v0.w;
        a.x += v1.x; a.y += v1.y; a.z += v1.z; a.w += v1.w;
        a.x += v2.x; a.y += v2.y; a.z += v2.z; a.w += v2.w;
        a.x += v3.x; a.y += v3.y; a.z += v3.z; a.w += v3.w;
    }
    for (; k < n; k++) {
        float4 v = xin[cj[k] * 16 + l4];
        a.x += v.x; a.y += v.y; a.z += v.z; a.w += v.w;
    }

    float r = g_rdeg[row];
    float4 u = make_float4(a.x * r, a.y * r, a.z * r, a.w * r);

    int o = row * 16 + l4;
    if (layer != 2) {
        uout[o] = u;
    } else {
        float4 a0 = g_u0[o];
        float4 a1 = g_u1[o];
        float4 a2 = g_u2[o];
        float s = g_sqdeg[row] * 0.25f;
        float4 res;
        res.x = (a0.x + a1.x + a2.x + u.x) * s;
        res.y = (a0.y + a1.y + a2.y + u.y) * s;
        res.z = (a0.z + a1.z + a2.z + u.z) * s;
        res.w = (a0.w + a1.w + a2.w + u.w) * s;
        ((float4*)dout)[o] = res;
    }
}

extern "C" void kernel_launch(void* const* d_in, const int* in_sizes, int n_in,
                              void* d_out, int out_size) {
    const int*   ei = (const int*)  d_in[0];   // edge_index int32 (2, NE)
    const float* ue = (const float*)d_in[1];   // user_emb (8000, 64)
    const float* ie = (const float*)d_in[2];   // item_emb (4000, 64)
    float* out = (float*)d_out;

    k_zero_adj <<<(NN * WROW / 4 + 255) / 256, 256>>>();
    k_set_edges<<<(NE + 255) / 256, 256>>>(ei);
    k_build    <<<NN, 64>>>(ue, ie);

    k_spmm<<<NN / RPB, 128>>>(0, nullptr);   // u0 -> u1
    k_spmm<<<NN / RPB, 128>>>(1, nullptr);   // u1 -> u2
    k_spmm<<<NN / RPB, 128>>>(2, out);       // u2 -> u3, fused final
}